// round 10
// baseline (speedup 1.0000x reference)
#include <cuda_runtime.h>

// LSTM: B=4096, T=256, F=18, H=64 (4H=256 gates i,f,g,o), classifier O=15.
// R10: occupancy-2 persistent kernel. 256 CTAs x 256 threads, ROWS=16 per CTA,
// 2 CTAs co-resident per SM (smem 112KB/CTA, <=128 regs). Warp (gsel,cq):
// gsel = k-half (A: k0..31+f0..8, B: k32..63+f9..17), cq = cell-quarter.
// Lane (tr,tc): rows 2tr..2tr+1, cells 16cq+4tc..+3. Weights gate-partitioned
// (each weight byte read by ONE warp, 64B/wavefront); h/x stored transposed
// for conflict-free LDS.128. Symmetric epilogue: A finalizes even local row,
// B odd. tanh.approx activations (5 MUFU/cell). f32x2 FMA throughout.

#define T_LEN 256
#define F_IN  18
#define H_DIM 64
#define G_DIM 256
#define O_DIM 15
#define ROWS  16
#define NTHR  256
#define NCTA  256
#define GK    32      // h-k steps per k-half
#define GF    9       // x-f steps per k-half
#define BST   18      // u64 stride of transposed act rows (16 + 2 pad)

typedef unsigned long long u64;

// ---- shared memory layout (bytes) ----
#define SM_WT    0                           // float Wt[82][256]      = 83968
#define SM_HT    83968                       // u64 hT[64][18]         = 9216
#define SM_XT    (SM_HT + 9216)              // u64 xT[2][18][18]      = 5184
#define SM_RED   (SM_XT + 5184)              // u64 red[2][8][128]     = 16384 (bias staging aliased)
#define SM_TOTAL (SM_RED + 16384)            // 114752  (112.1 KB) -> 2 CTAs/SM

__device__ __forceinline__ u64 pack2(float x, float y) {
    u64 r; asm("mov.b64 %0, {%1, %2};" : "=l"(r) : "f"(x), "f"(y)); return r;
}
__device__ __forceinline__ void unpack2(u64 v, float& x, float& y) {
    asm("mov.b64 {%0, %1}, %2;" : "=f"(x), "=f"(y) : "l"(v));
}
__device__ __forceinline__ void fma2(u64& d, u64 a, u64 b) {
    asm("fma.rn.f32x2 %0, %1, %2, %3;" : "=l"(d) : "l"(a), "l"(b), "l"(d));
}
__device__ __forceinline__ void add2(u64& d, u64 a) {
    asm("add.rn.f32x2 %0, %1, %2;" : "=l"(d) : "l"(d), "l"(a));
}
__device__ __forceinline__ ulonglong2 lds_v2(const u64* p) {
    return *(const ulonglong2*)p;    // LDS.128 (16B-aligned by construction)
}

// hardware tanh (MUFU.TANH): 1 MUFU op, ~5e-4 max abs err
__device__ __forceinline__ float tanh_(float x) {
    float r; asm("tanh.approx.f32 %0, %1;" : "=f"(r) : "f"(x)); return r;
}
// sigmoid via tanh: sig(x) = 0.5*tanh(x/2) + 0.5
__device__ __forceinline__ float sig_(float x) {
    return fmaf(0.5f, tanh_(0.5f * x), 0.5f);
}

__global__ void __launch_bounds__(NTHR, 2) lstm_kernel(
    const float* __restrict__ X,      // [B,T,F]
    const float* __restrict__ W_ih,   // [4H,F]
    const float* __restrict__ W_hh,   // [4H,H]
    const float* __restrict__ b_ih,   // [4H]
    const float* __restrict__ b_hh,   // [4H]
    const float* __restrict__ W_cls,  // [O,H]
    const float* __restrict__ b_cls,  // [O]
    float* __restrict__ out)          // [B,O]
{
    extern __shared__ char sm[];
    float* Wt = (float*)(sm + SM_WT);   // Wt[k][g]: k<64 -> W_hh[g][k]; k=64+f -> W_ih[g][f]
    u64*   hT = (u64*)  (sm + SM_HT);   // hT[cell][row], duplicated float2
    u64*   red= (u64*)  (sm + SM_RED);  // red[writer][i][lane]; bias staging aliased at setup
    float* bs = (float*)(sm + SM_RED);  // alias (setup only)

    const int tid  = threadIdx.x;
    const int lt   = tid & 127;
    const int gsel = tid >> 7;          // k-half: 0 = A, 1 = B
    const int cq   = (tid >> 5) & 3;    // cell quarter: cells 16cq..16cq+15
    const int lane = tid & 31;
    const int tr   = lane >> 2;         // rows 2tr, 2tr+1
    const int tc   = lane & 3;          // cells 16cq + 4tc .. +3
    const int row0 = blockIdx.x * ROWS;
    const int wcol = 8 * cq + 2 * tc;   // u64 column of my gate quad inside a q-block

    // ---- one-time setup ----
    for (int i = tid; i < H_DIM * G_DIM; i += NTHR) {
        int k = i >> 8, g = i & 255;
        Wt[k * G_DIM + g] = W_hh[g * H_DIM + k];
    }
    for (int i = tid; i < F_IN * G_DIM; i += NTHR) {
        int f = i >> 8, g = i & 255;
        Wt[(H_DIM + f) * G_DIM + g] = W_ih[g * F_IN + f];
    }
    for (int g = tid; g < G_DIM; g += NTHR) bs[g] = b_ih[g] + b_hh[g];
    for (int i = tid; i < H_DIM * BST; i += NTHR) hT[i] = 0ull;   // h(-1)=0

    // X prefetch mapping: 2 slots cover 16x18 = 288 elements
    int pb[2], pf[2]; bool pv[2];
#pragma unroll
    for (int m = 0; m < 2; m++) {
        int e = tid + NTHR * m;
        pv[m] = (e < ROWS * F_IN);
        int b = e / F_IN;
        pb[m] = b;
        pf[m] = e - b * F_IN;
    }
    const float* Xbase = X + (long long)row0 * T_LEN * F_IN;

    // stage x(0) into xT[0]  (xT[f][row], duplicated)
    {
        u64* x0 = (u64*)(sm + SM_XT);
#pragma unroll
        for (int m = 0; m < 2; m++)
            if (pv[m]) {
                float v = Xbase[(long long)pb[m] * (T_LEN * F_IN) + pf[m]];
                x0[pf[m] * BST + pb[m]] = pack2(v, v);
            }
    }
    __syncthreads();   // bs visible

    // gate-pair biases: biasv[q][c] covers gates 64q + 16cq + 4tc + {2c,2c+1}
    u64 biasv[4][2];
#pragma unroll
    for (int q = 0; q < 4; q++)
#pragma unroll
        for (int c = 0; c < 2; c++)
            biasv[q][c] = ((const u64*)bs)[q * 32 + wcol + c];

    // cell state: this thread finalizes row 2tr + gsel, cells 16cq+4tc+{0..3}
    float creg[4];
#pragma unroll
    for (int c = 0; c < 4; c++) creg[c] = 0.0f;

    const u64* wt2 = (const u64*)Wt;    // Wt row k = 128 u64
    const int kh0 = gsel * GK;
    const int xf0 = gsel * GF;
    const int abase = 2 * tr;
    const int brow = 2 * tr + gsel;     // the row I finalize
    const int j0 = 16 * cq + 4 * tc;    // my first cell
    u64* redW = red + gsel * (8 * 128);
    const u64* redR = red + (gsel ^ 1) * (8 * 128);
    int buf = 0;

    __syncthreads();   // biasv reads done before red reuse; x(0), h(-1) visible

    // ================= time loop =================
    for (int t = 0; t < T_LEN; ++t) {
        const u64* xb  = (const u64*)(sm + SM_XT) + buf * (F_IN * BST);
        u64*       xb2 = (u64*)(sm + SM_XT) + (buf ^ 1) * (F_IN * BST);

        // issue x(t+1) global loads first
        float xp[2];
        if (t + 1 < T_LEN) {
#pragma unroll
            for (int m = 0; m < 2; m++)
                xp[m] = pv[m]
                    ? Xbase[(long long)pb[m] * (T_LEN * F_IN) + (t + 1) * F_IN + pf[m]]
                    : 0.0f;
        }

        // bias into the row THIS half finalizes; zero in the other
        u64 acc[2][4][2];
#pragma unroll
        for (int r = 0; r < 2; r++)
#pragma unroll
            for (int q = 0; q < 4; q++)
#pragma unroll
                for (int c = 0; c < 2; c++)
                    acc[r][q][c] = (r == gsel) ? biasv[q][c] : 0ull;

        // ---- x-part: this half's 9 f's (reads only x(t) -> before bar1) ----
#pragma unroll 3
        for (int ff = 0; ff < GF; ff++) {
            int f = xf0 + ff;
            ulonglong2 A = lds_v2(xb + f * BST + abase);
            const u64* wrow = wt2 + (H_DIM + f) * 128 + wcol;
#pragma unroll
            for (int q = 0; q < 4; q++) {
                ulonglong2 w = lds_v2(wrow + q * 32);
                fma2(acc[0][q][0], A.x, w.x); fma2(acc[0][q][1], A.x, w.y);
                fma2(acc[1][q][0], A.y, w.x); fma2(acc[1][q][1], A.y, w.y);
            }
        }

        __syncthreads();   // bar1: h(t-1) stores visible; red(t-1) readers done

        // ---- h-part: this half's 32 k's, transposed conflict-free acts ----
#pragma unroll 4
        for (int kk = 0; kk < GK; kk++) {
            int k = kh0 + kk;
            ulonglong2 A = lds_v2(hT + k * BST + abase);
            const u64* wrow = wt2 + k * 128 + wcol;
#pragma unroll
            for (int q = 0; q < 4; q++) {
                ulonglong2 w = lds_v2(wrow + q * 32);
                fma2(acc[0][q][0], A.x, w.x); fma2(acc[0][q][1], A.x, w.y);
                fma2(acc[1][q][0], A.y, w.x); fma2(acc[1][q][1], A.y, w.y);
            }
        }

        // ---- publish partials for the row the OTHER half finalizes ----
        if (gsel == 0) {   // A finalizes local r=0, sends r=1
#pragma unroll
            for (int q = 0; q < 4; q++)
#pragma unroll
                for (int c = 0; c < 2; c++)
                    redW[(q * 2 + c) * 128 + lt] = acc[1][q][c];
        } else {           // B finalizes local r=1, sends r=0
#pragma unroll
            for (int q = 0; q < 4; q++)
#pragma unroll
                for (int c = 0; c < 2; c++)
                    redW[(q * 2 + c) * 128 + lt] = acc[0][q][c];
        }

        // publish x(t+1) before bar2
        if (t + 1 < T_LEN) {
#pragma unroll
            for (int m = 0; m < 2; m++)
                if (pv[m]) xb2[pf[m] * BST + pb[m]] = pack2(xp[m], xp[m]);
        }

        __syncthreads();   // bar2: partials + x(t+1) visible; h readers done

        // ---- gather my row (static idx, warp-uniform branch) + combine ----
        u64 myacc[4][2];
        if (gsel == 0) {
#pragma unroll
            for (int q = 0; q < 4; q++)
#pragma unroll
                for (int c = 0; c < 2; c++) myacc[q][c] = acc[0][q][c];
        } else {
#pragma unroll
            for (int q = 0; q < 4; q++)
#pragma unroll
                for (int c = 0; c < 2; c++) myacc[q][c] = acc[1][q][c];
        }
#pragma unroll
        for (int q = 0; q < 4; q++)
#pragma unroll
            for (int c = 0; c < 2; c++)
                add2(myacc[q][c], redR[(q * 2 + c) * 128 + lt]);

        // ---- cell update + publish h(t): row brow, cells j0..j0+3 ----
        {
            float gv[4][4];   // [q][cell]
#pragma unroll
            for (int q = 0; q < 4; q++) {
                unpack2(myacc[q][0], gv[q][0], gv[q][1]);
                unpack2(myacc[q][1], gv[q][2], gv[q][3]);
            }
#pragma unroll
            for (int c = 0; c < 4; c++) {
                float iv = sig_(gv[0][c]);
                float fv = sig_(gv[1][c]);
                float gg = tanh_(gv[2][c]);
                float ov = sig_(gv[3][c]);
                float cc = fv * creg[c] + iv * gg;
                creg[c] = cc;
                float hv = ov * tanh_(cc);
                hT[(j0 + c) * BST + brow] = pack2(hv, hv);
            }
        }

        buf ^= 1;
    }

    // ---- classifier head on final h (hT[cell][row]); W_cls/b_cls from gmem ----
    __syncthreads();
    const float* hf = (const float*)hT;

    for (int e = tid; e < ROWS * O_DIM; e += NTHR) {
        int b = e / O_DIM, o = e - b * O_DIM;
        float s = b_cls[o];
#pragma unroll
        for (int j = 0; j < H_DIM; j++)
            s += hf[(j * BST + b) * 2] * W_cls[o * H_DIM + j];
        out[(long long)(row0 + b) * O_DIM + o] = s;
    }
}

extern "C" void kernel_launch(void* const* d_in, const int* in_sizes, int n_in,
                              void* d_out, int out_size)
{
    const float* X     = (const float*)d_in[0];
    const float* W_ih  = (const float*)d_in[1];
    const float* W_hh  = (const float*)d_in[2];
    const float* b_ih  = (const float*)d_in[3];
    const float* b_hh  = (const float*)d_in[4];
    const float* W_cls = (const float*)d_in[5];
    const float* b_cls = (const float*)d_in[6];

    cudaFuncSetAttribute(lstm_kernel,
                         cudaFuncAttributeMaxDynamicSharedMemorySize, SM_TOTAL);
    lstm_kernel<<<NCTA, NTHR, SM_TOTAL>>>(X, W_ih, W_hh, b_ih, b_hh,
                                          W_cls, b_cls, (float*)d_out);
}